// round 2
// baseline (speedup 1.0000x reference)
#include <cuda_runtime.h>
#include <math.h>

#define Bn 32
#define Tn 2048
#define Dn 256
#define Hn 256
#define An 128
#define Cn 4367
#define CP 4368
#define NSTEPS 22
#define G3H 768

// ---------------- scratch (static device globals; no allocation) ----------------
__device__ float g_xWT[(size_t)Bn * An * Tn];   // [b][a][t]  ~33.5 MB
__device__ float g_h[Bn * Hn];
__device__ float g_q[Bn * An];
__device__ float g_ctx[Bn * Dn];                // unnormalized ctx accumulator
__device__ float g_sumw[Bn];
__device__ float g_gi[Bn * G3H];
__device__ float g_gh[Bn * G3H];
__device__ float g_WihT[Dn * G3H];              // [k][j]
__device__ float g_WhhT[Hn * G3H];              // [k][j]
__device__ float g_WclsT[Hn * CP];              // [k][c] padded to 4368

// ---------------- init: transposes + zero state ----------------
__global__ void k_init(const float* __restrict__ W_ih,
                       const float* __restrict__ W_hh,
                       const float* __restrict__ W_cls) {
    int idx = blockIdx.x * blockDim.x + threadIdx.x;
    int stride = gridDim.x * blockDim.x;
    for (int i = idx; i < G3H * Dn; i += stride) {
        int j = i / Dn, k = i % Dn;
        g_WihT[k * G3H + j] = W_ih[i];
        g_WhhT[k * G3H + j] = W_hh[i];
    }
    for (int i = idx; i < Cn * Hn; i += stride) {
        int c = i / Hn, k = i % Hn;
        g_WclsT[k * CP + c] = W_cls[i];
    }
    for (int i = idx; i < Bn * Hn; i += stride) { g_h[i] = 0.f; g_ctx[i] = 0.f; }
    for (int i = idx; i < Bn * An; i += stride) g_q[i] = 0.f;
    if (idx < Bn) g_sumw[idx] = 0.f;
}

// ---------------- xW GEMM: [65536,256] @ [256,128] -> transposed [b][a][t] ----------------
__global__ __launch_bounds__(256) void k_xw(const float* __restrict__ x,
                                            const float* __restrict__ Wx) {
    __shared__ float As[128][9];   // [t][k] padded
    __shared__ float Bs[8][128];   // [k][a]
    int rb = blockIdx.x;           // 512 blocks, 128 rows each (t-tiles never cross b)
    int row0 = rb * 128;
    int b = row0 / Tn;
    int t0 = row0 % Tn;
    int tid = threadIdx.x;
    int tt = tid / 16;             // t group (8 rows)
    int ta = tid % 16;             // a group (8 cols)

    float acc[8][8];
#pragma unroll
    for (int i = 0; i < 8; i++)
#pragma unroll
        for (int j = 0; j < 8; j++) acc[i][j] = 0.f;

    int lr = tid >> 1;             // As load: row
    int lp = tid & 1;              // half (2 float4 per row of 8 k)
    int lk = tid >> 5;             // Bs load: k row
    int la = tid & 31;             // float4 col

    for (int k0 = 0; k0 < 256; k0 += 8) {
        float4 xa = *(const float4*)(x + (size_t)(row0 + lr) * Dn + k0 + lp * 4);
        As[lr][lp * 4 + 0] = xa.x; As[lr][lp * 4 + 1] = xa.y;
        As[lr][lp * 4 + 2] = xa.z; As[lr][lp * 4 + 3] = xa.w;
        float4 wv = *(const float4*)(Wx + (size_t)(k0 + lk) * An + la * 4);
        *(float4*)(&Bs[lk][la * 4]) = wv;
        __syncthreads();
#pragma unroll
        for (int kk = 0; kk < 8; kk++) {
            float af[8], bf[8];
#pragma unroll
            for (int i = 0; i < 8; i++) af[i] = As[tt * 8 + i][kk];
#pragma unroll
            for (int j = 0; j < 8; j++) bf[j] = Bs[kk][ta * 8 + j];
#pragma unroll
            for (int i = 0; i < 8; i++)
#pragma unroll
                for (int j = 0; j < 8; j++) acc[i][j] += af[i] * bf[j];
        }
        __syncthreads();
    }
    // write transposed: [b][a][t], 8 consecutive t per thread -> 2x float4
#pragma unroll
    for (int j = 0; j < 8; j++) {
        int a = ta * 8 + j;
        float* dst = g_xWT + ((size_t)b * An + a) * Tn + t0 + tt * 8;
        float4 v0 = make_float4(acc[0][j], acc[1][j], acc[2][j], acc[3][j]);
        float4 v1 = make_float4(acc[4][j], acc[5][j], acc[6][j], acc[7][j]);
        *(float4*)dst = v0;
        *(float4*)(dst + 4) = v1;
    }
}

// ---------------- fused attention step: e -> w=exp(e) -> partial ctx/sumw ----------------
__global__ __launch_bounds__(256) void k_attn(const float* __restrict__ x,
                                              const float* __restrict__ v) {
    int b = blockIdx.y;            // 32
    int t0 = blockIdx.x * 256;     // 8 chunks of 256 t
    int tid = threadIdx.x;

    __shared__ float q_s[An];
    __shared__ float v_s[An];
    __shared__ float w_s[256];
    __shared__ float red[8];

    if (tid < An) { q_s[tid] = g_q[b * An + tid]; v_s[tid] = v[tid]; }
    __syncthreads();

    // phase A: e over A=128 (coalesced across t)
    const float* xw = g_xWT + (size_t)b * An * Tn + (t0 + tid);
    float e0 = 0.f, e1 = 0.f, e2 = 0.f, e3 = 0.f;
#pragma unroll 4
    for (int a = 0; a < An; a += 4) {
        float z0 = xw[(size_t)(a + 0) * Tn] + q_s[a + 0];
        float z1 = xw[(size_t)(a + 1) * Tn] + q_s[a + 1];
        float z2 = xw[(size_t)(a + 2) * Tn] + q_s[a + 2];
        float z3 = xw[(size_t)(a + 3) * Tn] + q_s[a + 3];
        float th0, th1, th2, th3;
        asm("tanh.approx.f32 %0, %1;" : "=f"(th0) : "f"(z0));
        asm("tanh.approx.f32 %0, %1;" : "=f"(th1) : "f"(z1));
        asm("tanh.approx.f32 %0, %1;" : "=f"(th2) : "f"(z2));
        asm("tanh.approx.f32 %0, %1;" : "=f"(th3) : "f"(z3));
        e0 += th0 * v_s[a + 0];
        e1 += th1 * v_s[a + 1];
        e2 += th2 * v_s[a + 2];
        e3 += th3 * v_s[a + 3];
    }
    // |e| <= sum|v| ~ 5 -> exp stable without max subtraction
    float w = __expf((e0 + e1) + (e2 + e3));
    w_s[tid] = w;

    float s = w;
#pragma unroll
    for (int o = 16; o > 0; o >>= 1) s += __shfl_xor_sync(0xffffffffu, s, o);
    if ((tid & 31) == 0) red[tid >> 5] = s;
    __syncthreads();
    if (tid == 0) {
        float tot = 0.f;
#pragma unroll
        for (int i = 0; i < 8; i++) tot += red[i];
        atomicAdd(&g_sumw[b], tot);
    }

    // phase B: partial ctx (d = tid), coalesced across d
    const float* xp = x + ((size_t)b * Tn + t0) * Dn + tid;
    float a0 = 0.f, a1 = 0.f, a2 = 0.f, a3 = 0.f;
#pragma unroll 4
    for (int t = 0; t < 256; t += 4) {
        a0 += w_s[t + 0] * xp[(size_t)(t + 0) * Dn];
        a1 += w_s[t + 1] * xp[(size_t)(t + 1) * Dn];
        a2 += w_s[t + 2] * xp[(size_t)(t + 2) * Dn];
        a3 += w_s[t + 3] * xp[(size_t)(t + 3) * Dn];
    }
    atomicAdd(&g_ctx[b * Dn + tid], (a0 + a1) + (a2 + a3));
}

// ---------------- GRU gate GEMMs: gi = ctx@W_ih^T+b_ih ; gh = h@W_hh^T+b_hh ----------------
__global__ __launch_bounds__(256) void k_gates(const float* __restrict__ b_ih,
                                               const float* __restrict__ b_hh) {
    int b = blockIdx.y;
    int tid = threadIdx.x;
    bool is_gi = (blockIdx.x < 3);
    int jj = (is_gi ? blockIdx.x : blockIdx.x - 3) * 256 + tid;  // 0..767

    __shared__ float src[256];
    src[tid] = is_gi ? g_ctx[b * Dn + tid] : g_h[b * Hn + tid];
    __syncthreads();

    const float* W = is_gi ? g_WihT : g_WhhT;
    float acc0 = 0.f, acc1 = 0.f;
#pragma unroll 8
    for (int k = 0; k < 256; k += 2) {
        acc0 += src[k] * W[(size_t)k * G3H + jj];
        acc1 += src[k + 1] * W[(size_t)(k + 1) * G3H + jj];
    }
    float acc = acc0 + acc1;
    if (is_gi) {
        float inv = 1.f / g_sumw[b];               // normalize ctx lazily
        g_gi[b * G3H + jj] = acc * inv + b_ih[jj];
    } else {
        g_gh[b * G3H + jj] = acc + b_hh[jj];
    }
}

// ---------------- GRU combine + h update + q = h@Wh + zero scratch ----------------
__global__ __launch_bounds__(256) void k_update(const float* __restrict__ Wh) {
    int b = blockIdx.x;
    int tid = threadIdx.x;     // 256 = H
    __shared__ float hs[256];

    float i_r = g_gi[b * G3H + tid];
    float i_z = g_gi[b * G3H + 256 + tid];
    float i_n = g_gi[b * G3H + 512 + tid];
    float h_r = g_gh[b * G3H + tid];
    float h_z = g_gh[b * G3H + 256 + tid];
    float h_n = g_gh[b * G3H + 512 + tid];
    float hprev = g_h[b * Hn + tid];

    float r = 1.f / (1.f + expf(-(i_r + h_r)));
    float z = 1.f / (1.f + expf(-(i_z + h_z)));
    float n = tanhf(i_n + r * h_n);
    float hn = (1.f - z) * n + z * hprev;

    g_h[b * Hn + tid] = hn;
    hs[tid] = hn;
    g_ctx[b * Dn + tid] = 0.f;            // reset for next step
    if (tid == 0) g_sumw[b] = 0.f;
    __syncthreads();

    if (tid < An) {                        // q[a] = sum_k hs[k] * Wh[k][a]
        float acc0 = 0.f, acc1 = 0.f;
#pragma unroll 8
        for (int k = 0; k < 256; k += 2) {
            acc0 += hs[k] * Wh[(size_t)k * An + tid];
            acc1 += hs[k + 1] * Wh[(size_t)(k + 1) * An + tid];
        }
        g_q[b * An + tid] = acc0 + acc1;
    }
}

// ---------------- classifier: logits[b, step, c] = h@W_cls^T + b_cls ----------------
__global__ __launch_bounds__(256) void k_cls(const float* __restrict__ b_cls,
                                             float* __restrict__ out, int step) {
    int c = blockIdx.x * 256 + threadIdx.x;
    int b0 = blockIdx.y * 8;
    __shared__ float hs[8 * 256];
    for (int i = threadIdx.x; i < 8 * 256; i += 256) hs[i] = g_h[b0 * Hn + i];
    __syncthreads();

    if (c < Cn) {
        float acc[8];
#pragma unroll
        for (int bb = 0; bb < 8; bb++) acc[bb] = 0.f;
#pragma unroll 4
        for (int k = 0; k < 256; k++) {
            float wv = g_WclsT[(size_t)k * CP + c];
#pragma unroll
            for (int bb = 0; bb < 8; bb++) acc[bb] += hs[bb * 256 + k] * wv;
        }
        float bias = b_cls[c];
#pragma unroll
        for (int bb = 0; bb < 8; bb++)
            out[((size_t)(b0 + bb) * NSTEPS + step) * Cn + c] = acc[bb] + bias;
    }
}

// ---------------- launch ----------------
extern "C" void kernel_launch(void* const* d_in, const int* in_sizes, int n_in,
                              void* d_out, int out_size) {
    const float* x     = (const float*)d_in[0];
    const float* Wx    = (const float*)d_in[1];
    const float* Wh    = (const float*)d_in[2];
    const float* v     = (const float*)d_in[3];
    const float* W_ih  = (const float*)d_in[4];
    const float* W_hh  = (const float*)d_in[5];
    const float* b_ih  = (const float*)d_in[6];
    const float* b_hh  = (const float*)d_in[7];
    const float* W_cls = (const float*)d_in[8];
    const float* b_cls = (const float*)d_in[9];
    float* out = (float*)d_out;

    k_init<<<1024, 256>>>(W_ih, W_hh, W_cls);
    k_xw<<<512, 256>>>(x, Wx);

    for (int s = 0; s < NSTEPS; s++) {
        k_attn<<<dim3(8, 32), 256>>>(x, v);
        k_gates<<<dim3(6, 32), 256>>>(b_ih, b_hh);
        k_update<<<32, 256>>>(Wh);
        k_cls<<<dim3(18, 4), 256>>>(b_cls, out, s);
    }
    (void)in_sizes; (void)n_in; (void)out_size;
}